// round 2
// baseline (speedup 1.0000x reference)
#include <cuda_runtime.h>
#include <cstdint>

// Shapes
#define NB 256
#define NF 8
#define NS 200
#define ND 64
#define NH 36
#define NBF (NB*NF)          // 2048
#define NSTAT (NF*NH)        // 288
#define EPS_V 1e-3f

// pass1 shared-memory layout (floats)
#define KPAD 68                              // key row pad: 4-way-max conflicts, 16B aligned
#define SM_QH_OFF 2304                       // after A (64*36)
#define SM_KEY_OFF 2352                      // 16B aligned
#define PASS1_SMEM_FLOATS (SM_KEY_OFF + NS*KPAD)   // 2352 + 13600 = 15952
#define PASS1_SMEM_BYTES  (PASS1_SMEM_FLOATS * 4)  // 63808

// Scratch (no allocations allowed -> __device__ globals)
__device__ float g_h[(size_t)NBF * NS * NH];       // 59 MB hidden activations
__device__ float g_psum[NBF * NH];                 // per-block partial sums
__device__ float g_psq[NBF * NH];                  // per-block partial sum-squares
__device__ float g_mean[NSTAT];
__device__ float g_inv[NSTAT];

union F4U2 { float4 f4; ulonglong2 u2; };

__device__ __forceinline__ unsigned long long pack2(float x) {
    unsigned long long r;
    asm("mov.b64 %0, {%1, %1};" : "=l"(r) : "f"(x));
    return r;
}
__device__ __forceinline__ void fma2(unsigned long long &acc,
                                     unsigned long long a,
                                     unsigned long long b) {
    // packed fp32x2 fma: 2x fp32 FMA throughput on sm_103a
    asm("fma.rn.f32x2 %0, %1, %2, %0;" : "+l"(acc) : "l"(a), "l"(b));
}

// FFMA-only sigmoid (no MUFU): sigma(z) = 1/(1 + 2^(-z*log2(e)))
// 2^x: split int/frac, degree-5 poly on [-0.5,0.5]; reciprocal: magic seed + 3 Newton.
__device__ __forceinline__ float fast_sigmoid(float z) {
    float x = -z * 1.4426950408889634f;
    x = fminf(fmaxf(x, -30.0f), 30.0f);
    float n = rintf(x);
    float f = x - n;
    float p = 0.0013333558f;
    p = fmaf(p, f, 0.009618129f);
    p = fmaf(p, f, 0.055504109f);
    p = fmaf(p, f, 0.24022651f);
    p = fmaf(p, f, 0.69314718f);
    p = fmaf(p, f, 1.0f);
    int ni = (int)n;
    float sc = __int_as_float((ni + 127) << 23);
    float e = p * sc;                 // e = exp(-z)
    float w = 1.0f + e;
    float r = __int_as_float(0x7EF311C3 - __float_as_int(w));  // ~1/w seed
    r = r * (2.0f - w * r);
    r = r * (2.0f - w * r);
    r = r * (2.0f - w * r);
    return r;
}

// ---------------------------------------------------------------------------
// Pass 1: per (b,f) block. h[s,:] = key[s,:] @ A + qh ; A = W_k - W_d,
// qh = q @ (W_q + W_d) + b_h. Store h to g_h, write per-block stat partials.
// ---------------------------------------------------------------------------
__global__ void __launch_bounds__(256) pass1_kernel(
    const float* __restrict__ q, const float* __restrict__ key,
    const float* __restrict__ W_h, const float* __restrict__ b_h)
{
    extern __shared__ float sm[];
    float* A_s   = sm;                 // [64][36]
    float* qh_s  = sm + SM_QH_OFF;     // [36]
    float* key_s = sm + SM_KEY_OFF;    // [200][68]
    float* h_st  = sm + SM_KEY_OFF;    // reused for h staging [200][36]

    const int tid = threadIdx.x;
    const int bf  = blockIdx.x;
    const int f   = bf & 7;
    const float* Wf = W_h + f * (3 * ND * NH);   // f*6912

    // A = W_h[f, 0:64, :] - W_h[f, 128:192, :]
    for (int i = tid; i < ND * NH; i += 256)
        A_s[i] = Wf[i] - Wf[2 * ND * NH + i];

    // stage key tile (coalesced float4 -> padded smem)
    const float4* kg = (const float4*)(key + (size_t)bf * (NS * ND));
    for (int i = tid; i < NS * ND / 4; i += 256) {
        float4 v = kg[i];
        int r  = i >> 4;        // row
        int d4 = i & 15;
        *(float4*)(key_s + r * KPAD + d4 * 4) = v;
    }

    // qh[hh] = b_h + sum_d q[d]*(W_q + W_d)
    if (tid < NH) {
        const float* qr = q + (size_t)bf * ND;
        float s = b_h[f * NH + tid];
        #pragma unroll 4
        for (int d = 0; d < ND; ++d)
            s += qr[d] * (Wf[(ND + d) * NH + tid] + Wf[(2 * ND + d) * NH + tid]);
        qh_s[tid] = s;
    }
    __syncthreads();

    unsigned long long acc[NH / 2];
    const int r = tid;
    if (r < NS) {
        #pragma unroll
        for (int j = 0; j < NH / 2; ++j)
            acc[j] = *(const unsigned long long*)(qh_s + 2 * j);
        const float* krow = key_s + r * KPAD;
        #pragma unroll 4
        for (int d4 = 0; d4 < 16; ++d4) {
            float4 k4 = *(const float4*)(krow + 4 * d4);
            float ks[4] = {k4.x, k4.y, k4.z, k4.w};
            #pragma unroll
            for (int e = 0; e < 4; ++e) {
                unsigned long long kk = pack2(ks[e]);
                const float4* arow = (const float4*)(A_s + (4 * d4 + e) * NH);
                #pragma unroll
                for (int j = 0; j < 9; ++j) {
                    F4U2 u; u.f4 = arow[j];
                    fma2(acc[2 * j],     u.u2.x, kk);
                    fma2(acc[2 * j + 1], u.u2.y, kk);
                }
            }
        }
    }
    __syncthreads();   // key_s no longer needed; safe to overwrite with h

    if (r < NS) {
        float* hrow = h_st + r * NH;
        #pragma unroll
        for (int j = 0; j < NH / 2; ++j) {
            F4U2 u; u.u2.x = acc[j];
            float2 v; v.x = u.f4.x; v.y = u.f4.y;
            *(float2*)(hrow + 2 * j) = v;
        }
    }
    __syncthreads();

    // coalesced copy-out of h
    {
        const float4* hs4 = (const float4*)h_st;
        float4* hg4 = (float4*)(g_h + (size_t)bf * (NS * NH));
        for (int i = tid; i < NS * NH / 4; i += 256)
            hg4[i] = hs4[i];
    }
    // per-block partial stats (deterministic)
    if (tid < NH) {
        float s = 0.f, qq = 0.f;
        #pragma unroll 4
        for (int rr = 0; rr < NS; ++rr) {
            float v = h_st[rr * NH + tid];
            s += v; qq += v * v;
        }
        g_psum[bf * NH + tid] = s;
        g_psq [bf * NH + tid] = qq;
    }
}

// ---------------------------------------------------------------------------
// Stats finalize: one block per (f,hh); reduce 256 b-partials.
// ---------------------------------------------------------------------------
__global__ void __launch_bounds__(256) kstats_kernel()
{
    __shared__ float rs[256], rq[256];
    const int col = blockIdx.x;           // f*36 + hh
    const int f = col / NH, hh = col - f * NH;
    const int t = threadIdx.x;            // t = b
    const int idx = (t * NF + f) * NH + hh;
    rs[t] = g_psum[idx];
    rq[t] = g_psq[idx];
    __syncthreads();
    for (int off = 128; off > 0; off >>= 1) {
        if (t < off) { rs[t] += rs[t + off]; rq[t] += rq[t + off]; }
        __syncthreads();
    }
    if (t == 0) {
        const float invN = 1.0f / (float)(NB * NS);
        float mean = rs[0] * invN;
        float var  = rq[0] * invN - mean * mean;
        g_mean[col] = mean;
        g_inv[col]  = rsqrtf(var + EPS_V);
    }
}

// ---------------------------------------------------------------------------
// Pass 3: gate + scores + masked softmax + attn @ key. One block per (b,f).
// ---------------------------------------------------------------------------
__global__ void __launch_bounds__(256) pass3_kernel(
    const float* __restrict__ key, const float* __restrict__ alpha,
    const float* __restrict__ W_o, const float* __restrict__ b_o,
    const int* __restrict__ seqnum, float* __restrict__ out)
{
    __shared__ float h_sm[NS * NH];
    __shared__ float inv_s[NH], nm_s[NH], wo_s[NH];
    __shared__ float sc[NS];
    __shared__ float red[256];
    __shared__ float opart[256];

    const int tid = threadIdx.x;
    const int bf  = blockIdx.x;
    const int f   = bf & 7;
    const int n   = seqnum[bf];

    {
        const float4* hg4 = (const float4*)(g_h + (size_t)bf * (NS * NH));
        for (int i = tid; i < NS * NH / 4; i += 256)
            ((float4*)h_sm)[i] = hg4[i];
    }
    if (tid < NH) {
        float m  = g_mean[f * NH + tid];
        float iv = g_inv [f * NH + tid];
        inv_s[tid] = iv;
        nm_s[tid]  = -m * iv;
        wo_s[tid]  = W_o[f * NH + tid];
    }
    const float al  = alpha[f];
    const float oma = 1.0f - al;
    __syncthreads();

    float score = -3.0e38f;
    if (tid < n) {
        float s = b_o[f];
        const float* hr = h_sm + tid * NH;
        #pragma unroll 6
        for (int j = 0; j < NH; ++j) {
            float v = hr[j];
            float z = fmaf(v, inv_s[j], nm_s[j]);
            float p = fast_sigmoid(z);
            float g = fmaf(oma, p, al) * v;
            s = fmaf(g, wo_s[j], s);
        }
        score = s;
    }
    // block max
    red[tid] = score;
    __syncthreads();
    for (int off = 128; off > 0; off >>= 1) {
        if (tid < off) red[tid] = fmaxf(red[tid], red[tid + off]);
        __syncthreads();
    }
    const float mx = red[0];
    __syncthreads();
    // exp + block sum
    float e = 0.0f;
    if (tid < n) {
        e = __expf(score - mx);
        sc[tid] = e;
    }
    red[tid] = e;
    __syncthreads();
    for (int off = 128; off > 0; off >>= 1) {
        if (tid < off) red[tid] += red[tid + off];
        __syncthreads();
    }
    const float denom = red[0];

    // out[d] = (sum_s e_s * key[s,d]) / denom
    const int d = tid & 63;
    const int g = tid >> 6;
    const float* kb = key + (size_t)bf * (NS * ND);
    float a0 = 0.0f;
    for (int s = g; s < n; s += 4)
        a0 = fmaf(sc[s], kb[s * ND + d], a0);
    opart[tid] = a0;
    __syncthreads();
    if (tid < ND) {
        float o = opart[tid] + opart[tid + 64] + opart[tid + 128] + opart[tid + 192];
        out[(size_t)bf * ND + tid] = o / denom;
    }
}

// ---------------------------------------------------------------------------
extern "C" void kernel_launch(void* const* d_in, const int* in_sizes, int n_in,
                              void* d_out, int out_size)
{
    const float* q      = (const float*)d_in[0];
    const float* key    = (const float*)d_in[1];
    const float* W_h    = (const float*)d_in[2];
    const float* b_h    = (const float*)d_in[3];
    const float* alpha  = (const float*)d_in[4];
    const float* W_o    = (const float*)d_in[5];
    const float* b_o    = (const float*)d_in[6];
    const int*   seqn   = (const int*)d_in[7];
    float* out = (float*)d_out;

    cudaFuncSetAttribute(pass1_kernel,
                         cudaFuncAttributeMaxDynamicSharedMemorySize,
                         PASS1_SMEM_BYTES);

    pass1_kernel<<<NBF, 256, PASS1_SMEM_BYTES>>>(q, key, W_h, b_h);
    kstats_kernel<<<NSTAT, 256>>>();
    pass3_kernel<<<NBF, 256>>>(key, alpha, W_o, b_o, seqn, out);
}

// round 3
// speedup vs baseline: 1.1052x; 1.1052x over previous
#include <cuda_runtime.h>
#include <cstdint>

// Shapes
#define NB 256
#define NF 8
#define NS 200
#define ND 64
#define NH 36
#define NBF (NB*NF)          // 2048
#define NSTAT (NF*NH)        // 288
#define EPS_V 1e-3f

// ---- pass1 shared memory layout (floats) ----
// A_s:   [0, 2560)        A as [k][2 halves][20 pad], 64*40
// qh_s:  [2560, 2600)     36 + pad
// sp_s:  [2600, 3176)     576 scratch (qh partials, then stats partials)
// key_s: [3200, 16800)    [200][68]  (16B aligned base; reused as h staging [200][36])
#define SM_A 0
#define SM_QH 2560
#define SM_SP 2600
#define SM_KEY 3200
#define KPAD 68
#define PASS1_SMEM_FLOATS (SM_KEY + NS*KPAD)        // 16800
#define PASS1_SMEM_BYTES  (PASS1_SMEM_FLOATS * 4)   // 67200

#define P1_THREADS 416

// Scratch (no allocations allowed -> __device__ globals)
__device__ float g_h[(size_t)NBF * NS * NH];       // 59 MB hidden activations
__device__ float g_psum[NBF * NH];
__device__ float g_psq[NBF * NH];
__device__ float g_mean[NSTAT];
__device__ float g_inv[NSTAT];

union F4U2 { float4 f4; ulonglong2 u2; };
union F2U1 { float2 f2; unsigned long long u; };

__device__ __forceinline__ unsigned long long pack2(float x) {
    unsigned long long r;
    asm("mov.b64 %0, {%1, %1};" : "=l"(r) : "f"(x));
    return r;
}
__device__ __forceinline__ void fma2(unsigned long long &acc,
                                     unsigned long long a,
                                     unsigned long long b) {
    asm("fma.rn.f32x2 %0, %1, %2, %0;" : "+l"(acc) : "l"(a), "l"(b));
}

// FFMA-only sigmoid (no MUFU)
__device__ __forceinline__ float fast_sigmoid(float z) {
    float x = -z * 1.4426950408889634f;
    x = fminf(fmaxf(x, -30.0f), 30.0f);
    float n = rintf(x);
    float f = x - n;
    float p = 0.0013333558f;
    p = fmaf(p, f, 0.009618129f);
    p = fmaf(p, f, 0.055504109f);
    p = fmaf(p, f, 0.24022651f);
    p = fmaf(p, f, 0.69314718f);
    p = fmaf(p, f, 1.0f);
    int ni = (int)n;
    float sc = __int_as_float((ni + 127) << 23);
    float e = p * sc;                 // exp(-z)
    float w = 1.0f + e;
    float r = __int_as_float(0x7EF311C3 - __float_as_int(w));
    r = r * (2.0f - w * r);
    r = r * (2.0f - w * r);
    return r;
}

// ---------------------------------------------------------------------------
// Pass 1: h[s,:] = key[s,:] @ A + qh ; A = W_k - W_d, qh = q@(W_q+W_d)+b_h.
// Thread = (row, col-half). Store h to g_h + per-block stat partials.
// ---------------------------------------------------------------------------
__global__ void __launch_bounds__(P1_THREADS, 2) pass1_kernel(
    const float* __restrict__ q, const float* __restrict__ key,
    const float* __restrict__ W_h, const float* __restrict__ b_h)
{
    extern __shared__ float sm[];
    float* A_s   = sm + SM_A;       // [64][40]  (cols 36..39 zero)
    float* qh_s  = sm + SM_QH;      // [36]
    float* sp_s  = sm + SM_SP;      // [576]
    float* key_s = sm + SM_KEY;     // [200][68]
    float* h_st  = sm + SM_KEY;     // reuse: [200][36]

    const int t  = threadIdx.x;
    const int bf = blockIdx.x;
    const int f  = bf & 7;
    const float* Wf = W_h + f * (3 * ND * NH);

    // A_s[k][half*20 + c] = W_k - W_d (c<18), pad zeros
    for (int i = t; i < ND * 40; i += P1_THREADS) {
        int k = i / 40, c = i % 40;
        int half = c / 20, cc = c % 20;
        float v = 0.0f;
        if (cc < 18) {
            int j = half * 18 + cc;
            v = Wf[k * NH + j] - Wf[(2 * ND + k) * NH + j];
        }
        A_s[i] = v;
    }

    // key tile -> padded smem (coalesced float4)
    const float4* kg = (const float4*)(key + (size_t)bf * (NS * ND));
    for (int i = t; i < NS * ND / 4; i += P1_THREADS) {
        float4 v = kg[i];
        int r = i >> 4, d4 = i & 15;
        *(float4*)(key_s + r * KPAD + d4 * 4) = v;
    }

    // qh partials: 288 threads, 8 d-chunks per col
    if (t < 288) {
        int hh = t >> 3, c = t & 7;
        const float* qr = q + (size_t)bf * ND;
        float s = 0.0f;
        #pragma unroll
        for (int dd = 0; dd < 8; ++dd) {
            int d = c * 8 + dd;
            s += qr[d] * (Wf[(ND + d) * NH + hh] + Wf[(2 * ND + d) * NH + hh]);
        }
        sp_s[t] = s;
    }
    __syncthreads();

    if (t < NH) {
        float s = b_h[f * NH + t];
        #pragma unroll
        for (int c = 0; c < 8; ++c) s += sp_s[t * 8 + c];
        qh_s[t] = s;
    }
    __syncthreads();

    // ---- main GEMM: 400 workers, thread=(row, half), 9 fma2 accs ----
    unsigned long long acc[9];
    const int half = (t >= 200) ? 1 : 0;
    const int r = t - half * 200;
    const bool work = (t < 400);
    if (work) {
        #pragma unroll
        for (int j = 0; j < 9; ++j)
            acc[j] = *(const unsigned long long*)(qh_s + half * 18 + 2 * j);
        const float* krow = key_s + r * KPAD;
        #pragma unroll 2
        for (int k0 = 0; k0 < ND; k0 += 4) {
            float4 k4 = *(const float4*)(krow + k0);
            const float kk4[4] = {k4.x, k4.y, k4.z, k4.w};
            #pragma unroll
            for (int e = 0; e < 4; ++e) {
                unsigned long long kk = pack2(kk4[e]);
                const float* ar = A_s + (k0 + e) * 40 + half * 20;
                F4U2 a01; a01.f4 = *(const float4*)(ar);
                F4U2 a23; a23.f4 = *(const float4*)(ar + 4);
                F4U2 a45; a45.f4 = *(const float4*)(ar + 8);
                F4U2 a67; a67.f4 = *(const float4*)(ar + 12);
                F2U1 a8;  a8.f2  = *(const float2*)(ar + 16);
                fma2(acc[0], a01.u2.x, kk);
                fma2(acc[1], a01.u2.y, kk);
                fma2(acc[2], a23.u2.x, kk);
                fma2(acc[3], a23.u2.y, kk);
                fma2(acc[4], a45.u2.x, kk);
                fma2(acc[5], a45.u2.y, kk);
                fma2(acc[6], a67.u2.x, kk);
                fma2(acc[7], a67.u2.y, kk);
                fma2(acc[8], a8.u,     kk);
            }
        }
    }
    __syncthreads();   // done reading key_s; safe to overwrite with h

    if (work) {
        float* hr = h_st + r * NH + half * 18;
        #pragma unroll
        for (int j = 0; j < 9; ++j) {
            F2U1 u; u.u = acc[j];
            *(float2*)(hr + 2 * j) = u.f2;
        }
    }
    __syncthreads();

    // coalesced copy-out of h
    {
        const float4* hs4 = (const float4*)h_st;
        float4* hg4 = (float4*)(g_h + (size_t)bf * (NS * NH));
        for (int i = t; i < NS * NH / 4; i += P1_THREADS)
            hg4[i] = hs4[i];
    }
    // per-block stat partials: 288 threads = 36 cols x 8 row-chunks of 25
    if (t < 288) {
        int hh = t >> 3, c = t & 3; // note: 8 chunks -> use t&7
        c = t & 7;
        float s = 0.f, qq = 0.f;
        #pragma unroll 5
        for (int rr = c * 25; rr < c * 25 + 25; ++rr) {
            float v = h_st[rr * NH + hh];
            s += v; qq += v * v;
        }
        sp_s[t] = s;
        sp_s[288 + t] = qq;
    }
    __syncthreads();
    if (t < NH) {
        float s = 0.f, qq = 0.f;
        #pragma unroll
        for (int c = 0; c < 8; ++c) {
            s  += sp_s[t * 8 + c];
            qq += sp_s[288 + t * 8 + c];
        }
        g_psum[bf * NH + t] = s;
        g_psq [bf * NH + t] = qq;
    }
}

// ---------------------------------------------------------------------------
// Stats finalize
// ---------------------------------------------------------------------------
__global__ void __launch_bounds__(256) kstats_kernel()
{
    __shared__ float rs[256], rq[256];
    const int col = blockIdx.x;           // f*36 + hh
    const int f = col / NH, hh = col - f * NH;
    const int t = threadIdx.x;            // t = b
    const int idx = (t * NF + f) * NH + hh;
    rs[t] = g_psum[idx];
    rq[t] = g_psq[idx];
    __syncthreads();
    for (int off = 128; off > 0; off >>= 1) {
        if (t < off) { rs[t] += rs[t + off]; rq[t] += rq[t + off]; }
        __syncthreads();
    }
    if (t == 0) {
        const float invN = 1.0f / (float)(NB * NS);
        float mean = rs[0] * invN;
        float var  = rq[0] * invN - mean * mean;
        g_mean[col] = mean;
        g_inv[col]  = rsqrtf(var + EPS_V);
    }
}

// ---------------------------------------------------------------------------
// Pass 3: gate + scores + masked softmax + attn @ key. One block per (b,f).
// ---------------------------------------------------------------------------
__global__ void __launch_bounds__(256) pass3_kernel(
    const float* __restrict__ key, const float* __restrict__ alpha,
    const float* __restrict__ W_o, const float* __restrict__ b_o,
    const int* __restrict__ seqnum, float* __restrict__ out)
{
    __shared__ float h_sm[NS * NH];
    __shared__ float inv_s[NH], nm_s[NH], wo_s[NH];
    __shared__ float sc[NS];
    __shared__ float red[256];
    __shared__ float opart[256];

    const int tid = threadIdx.x;
    const int bf  = blockIdx.x;
    const int f   = bf & 7;
    const int n   = seqnum[bf];

    {
        const float4* hg4 = (const float4*)(g_h + (size_t)bf * (NS * NH));
        for (int i = tid; i < NS * NH / 4; i += 256)
            ((float4*)h_sm)[i] = hg4[i];
    }
    if (tid < NH) {
        float m  = g_mean[f * NH + tid];
        float iv = g_inv [f * NH + tid];
        inv_s[tid] = iv;
        nm_s[tid]  = -m * iv;
        wo_s[tid]  = W_o[f * NH + tid];
    }
    const float al  = alpha[f];
    const float oma = 1.0f - al;
    __syncthreads();

    float score = -3.0e38f;
    if (tid < n) {
        float s = b_o[f];
        const float* hr = h_sm + tid * NH;
        #pragma unroll 6
        for (int j = 0; j < NH; ++j) {
            float v = hr[j];
            float z = fmaf(v, inv_s[j], nm_s[j]);
            float p = fast_sigmoid(z);
            float g = fmaf(oma, p, al) * v;
            s = fmaf(g, wo_s[j], s);
        }
        score = s;
    }
    red[tid] = score;
    __syncthreads();
    for (int off = 128; off > 0; off >>= 1) {
        if (tid < off) red[tid] = fmaxf(red[tid], red[tid + off]);
        __syncthreads();
    }
    const float mx = red[0];
    __syncthreads();
    float e = 0.0f;
    if (tid < n) {
        e = __expf(score - mx);
        sc[tid] = e;
    }
    red[tid] = e;
    __syncthreads();
    for (int off = 128; off > 0; off >>= 1) {
        if (tid < off) red[tid] += red[tid + off];
        __syncthreads();
    }
    const float denom = red[0];

    const int d = tid & 63;
    const int g = tid >> 6;
    const float* kb = key + (size_t)bf * (NS * ND);
    float a0 = 0.0f;
    for (int s = g; s < n; s += 4)
        a0 = fmaf(sc[s], kb[s * ND + d], a0);
    opart[tid] = a0;
    __syncthreads();
    if (tid < ND) {
        float o = opart[tid] + opart[tid + 64] + opart[tid + 128] + opart[tid + 192];
        out[(size_t)bf * ND + tid] = o / denom;
    }
}

// ---------------------------------------------------------------------------
extern "C" void kernel_launch(void* const* d_in, const int* in_sizes, int n_in,
                              void* d_out, int out_size)
{
    const float* q      = (const float*)d_in[0];
    const float* key    = (const float*)d_in[1];
    const float* W_h    = (const float*)d_in[2];
    const float* b_h    = (const float*)d_in[3];
    const float* alpha  = (const float*)d_in[4];
    const float* W_o    = (const float*)d_in[5];
    const float* b_o    = (const float*)d_in[6];
    const int*   seqn   = (const int*)d_in[7];
    float* out = (float*)d_out;

    cudaFuncSetAttribute(pass1_kernel,
                         cudaFuncAttributeMaxDynamicSharedMemorySize,
                         PASS1_SMEM_BYTES);

    pass1_kernel<<<NBF, P1_THREADS, PASS1_SMEM_BYTES>>>(q, key, W_h, b_h);
    kstats_kernel<<<NSTAT, 256>>>();
    pass3_kernel<<<NBF, 256>>>(key, alpha, W_o, b_o, seqn, out);
}

// round 4
// speedup vs baseline: 1.1365x; 1.0283x over previous
#include <cuda_runtime.h>
#include <cuda_fp16.h>
#include <cstdint>

// Shapes
#define NB 256
#define NF 8
#define NS 200
#define ND 64
#define NH 36
#define NBF (NB*NF)          // 2048
#define NSTAT (NF*NH)        // 288
#define EPS_V 1e-3f

// ---- pass1 shared memory layout (floats) ----
// A_s:   [0, 2560)      [k=64][half=2][20]  (cols 18,19 of each half zero)
// qh_s:  [2560, 2600)
// sp_s:  [2600, 3176)   scratch partials
// key_t: [3200, 16128)  transposed key [d=64][202]; reused as h staging [200][36]
#define SM_A 0
#define SM_QH 2560
#define SM_SP 2600
#define SM_KEY 3200
#define KTP 202
#define PASS1_SMEM_FLOATS (SM_KEY + ND*KTP)        // 16128
#define PASS1_SMEM_BYTES  (PASS1_SMEM_FLOATS * 4)  // 64512

#define P1_THREADS 256

// Scratch (no allocations -> __device__ globals)
__device__ __half2 g_h[(size_t)NBF * (NS * NH / 2)];   // fp16 hidden acts (29.5 MB)
__device__ float g_psum[NBF * NH];
__device__ float g_psq[NBF * NH];
__device__ float g_mean[NSTAT];
__device__ float g_inv[NSTAT];

union F4U2 { float4 f4; ulonglong2 u2; };
union F2U1 { float2 f2; unsigned long long u; };

__device__ __forceinline__ unsigned long long pack2(float x) {
    unsigned long long r;
    asm("mov.b64 %0, {%1, %1};" : "=l"(r) : "f"(x));
    return r;
}
__device__ __forceinline__ void fma2(unsigned long long &acc,
                                     unsigned long long a,
                                     unsigned long long b) {
    asm("fma.rn.f32x2 %0, %1, %2, %0;" : "+l"(acc) : "l"(a), "l"(b));
}

// FFMA-only sigmoid (no MUFU pressure)
__device__ __forceinline__ float fast_sigmoid(float z) {
    float x = -z * 1.4426950408889634f;
    x = fminf(fmaxf(x, -30.0f), 30.0f);
    float n = rintf(x);
    float f = x - n;
    float p = 0.0013333558f;
    p = fmaf(p, f, 0.009618129f);
    p = fmaf(p, f, 0.055504109f);
    p = fmaf(p, f, 0.24022651f);
    p = fmaf(p, f, 0.69314718f);
    p = fmaf(p, f, 1.0f);
    int ni = (int)n;
    float sc = __int_as_float((ni + 127) << 23);
    float e = p * sc;                 // exp(-z)
    float w = 1.0f + e;
    float r = __int_as_float(0x7EF311C3 - __float_as_int(w));
    r = r * (2.0f - w * r);
    r = r * (2.0f - w * r);
    return r;
}

// ---------------------------------------------------------------------------
// Pass 1: h[s,:] = key[s,:] @ A + qh ; A = W_k - W_d, qh = q@(W_q+W_d)+b_h.
// Thread = (row-pair, col-half): A loads amortized over 2 rows.
// ---------------------------------------------------------------------------
__global__ void __launch_bounds__(P1_THREADS, 2) pass1_kernel(
    const float* __restrict__ q, const float* __restrict__ key,
    const float* __restrict__ W_h, const float* __restrict__ b_h)
{
    extern __shared__ float sm[];
    float* A_s   = sm + SM_A;       // [64][40]
    float* qh_s  = sm + SM_QH;      // [36]
    float* sp_s  = sm + SM_SP;
    float* key_t = sm + SM_KEY;     // [64][202] transposed
    float* h_st  = sm + SM_KEY;     // reuse: [200][36]

    const int t  = threadIdx.x;
    const int bf = blockIdx.x;
    const int f  = bf & 7;
    const float* Wf = W_h + f * (3 * ND * NH);

    // A_s[k][half*20 + c] = W_k - W_d (c<18), pad zeros
    for (int i = t; i < ND * 40; i += P1_THREADS) {
        int k = i / 40, c = i % 40;
        int half = c / 20, cc = c % 20;
        float v = 0.0f;
        if (cc < 18) {
            int j = half * 18 + cc;
            v = Wf[k * NH + j] - Wf[(2 * ND + k) * NH + j];
        }
        A_s[i] = v;
    }

    // key -> transposed smem (coalesced LDG.128, scattered STS)
    const float4* kg = (const float4*)(key + (size_t)bf * (NS * ND));
    for (int i = t; i < NS * ND / 4; i += P1_THREADS) {
        float4 v = kg[i];
        int r = i >> 4, d = (i & 15) * 4;
        key_t[(d + 0) * KTP + r] = v.x;
        key_t[(d + 1) * KTP + r] = v.y;
        key_t[(d + 2) * KTP + r] = v.z;
        key_t[(d + 3) * KTP + r] = v.w;
    }

    // qh partials: 144 threads = 36 cols x 4 d-chunks of 16
    if (t < 144) {
        int hh = t >> 2, c = t & 3;
        const float* qr = q + (size_t)bf * ND;
        float s = 0.0f;
        #pragma unroll
        for (int dd = 0; dd < 16; ++dd) {
            int d = c * 16 + dd;
            s += qr[d] * (Wf[(ND + d) * NH + hh] + Wf[(2 * ND + d) * NH + hh]);
        }
        sp_s[t] = s;
    }
    __syncthreads();

    if (t < NH)
        qh_s[t] = b_h[f * NH + t] + sp_s[t*4] + sp_s[t*4+1] + sp_s[t*4+2] + sp_s[t*4+3];
    __syncthreads();

    // ---- main GEMM: 200 workers, thread=(row-pair, half), 2x9 fma2 accs ----
    unsigned long long accA[9], accB[9];
    const bool work = (t < 200);
    const int rp   = t % 100;          // rows 2rp, 2rp+1
    const int half = t / 100;
    if (work) {
        #pragma unroll
        for (int j = 0; j < 9; ++j) {
            unsigned long long init = *(const unsigned long long*)(qh_s + half * 18 + 2 * j);
            accA[j] = init; accB[j] = init;
        }
        const float* kt = key_t + 2 * rp;
        const float* ab = A_s + half * 20;
        #pragma unroll 4
        for (int k = 0; k < ND; ++k) {
            float2 kk = *(const float2*)(kt + k * KTP);
            unsigned long long kx = pack2(kk.x);
            unsigned long long ky = pack2(kk.y);
            const float* ar = ab + k * 40;
            F4U2 a01; a01.f4 = *(const float4*)(ar);
            F4U2 a23; a23.f4 = *(const float4*)(ar + 4);
            F4U2 a45; a45.f4 = *(const float4*)(ar + 8);
            F4U2 a67; a67.f4 = *(const float4*)(ar + 12);
            F2U1 a8;  a8.f2  = *(const float2*)(ar + 16);
            fma2(accA[0], a01.u2.x, kx);  fma2(accB[0], a01.u2.x, ky);
            fma2(accA[1], a01.u2.y, kx);  fma2(accB[1], a01.u2.y, ky);
            fma2(accA[2], a23.u2.x, kx);  fma2(accB[2], a23.u2.x, ky);
            fma2(accA[3], a23.u2.y, kx);  fma2(accB[3], a23.u2.y, ky);
            fma2(accA[4], a45.u2.x, kx);  fma2(accB[4], a45.u2.x, ky);
            fma2(accA[5], a45.u2.y, kx);  fma2(accB[5], a45.u2.y, ky);
            fma2(accA[6], a67.u2.x, kx);  fma2(accB[6], a67.u2.x, ky);
            fma2(accA[7], a67.u2.y, kx);  fma2(accB[7], a67.u2.y, ky);
            fma2(accA[8], a8.u,     kx);  fma2(accB[8], a8.u,     ky);
        }
    }
    __syncthreads();   // done reading key_t; safe to overwrite with h

    if (work) {
        float* hr0 = h_st + (2 * rp)     * NH + half * 18;
        float* hr1 = h_st + (2 * rp + 1) * NH + half * 18;
        #pragma unroll
        for (int j = 0; j < 9; ++j) {
            F2U1 u0; u0.u = accA[j];
            F2U1 u1; u1.u = accB[j];
            *(float2*)(hr0 + 2 * j) = u0.f2;
            *(float2*)(hr1 + 2 * j) = u1.f2;
        }
    }
    __syncthreads();

    // copy-out h as fp16 (coalesced half2 stores)
    {
        const float2* hs2 = (const float2*)h_st;
        __half2* hg = g_h + (size_t)bf * (NS * NH / 2);
        for (int i = t; i < NS * NH / 2; i += P1_THREADS)
            hg[i] = __float22half2_rn(hs2[i]);
    }
    // per-block stat partials (from fp32 smem): 144 threads = 36 cols x 4 chunks of 50
    if (t < 144) {
        int hh = t >> 2, c = t & 3;
        float s = 0.f, qq = 0.f;
        #pragma unroll 5
        for (int rr = c * 50; rr < c * 50 + 50; ++rr) {
            float v = h_st[rr * NH + hh];
            s += v; qq += v * v;
        }
        sp_s[t] = s;
        sp_s[160 + t] = qq;
    }
    __syncthreads();
    if (t < NH) {
        float s  = sp_s[t*4] + sp_s[t*4+1] + sp_s[t*4+2] + sp_s[t*4+3];
        float qq = sp_s[160 + t*4] + sp_s[160 + t*4+1] + sp_s[160 + t*4+2] + sp_s[160 + t*4+3];
        g_psum[bf * NH + t] = s;
        g_psq [bf * NH + t] = qq;
    }
}

// ---------------------------------------------------------------------------
// Stats finalize
// ---------------------------------------------------------------------------
__global__ void __launch_bounds__(256) kstats_kernel()
{
    __shared__ float rs[256], rq[256];
    const int col = blockIdx.x;           // f*36 + hh
    const int f = col / NH, hh = col - f * NH;
    const int t = threadIdx.x;            // t = b
    const int idx = (t * NF + f) * NH + hh;
    rs[t] = g_psum[idx];
    rq[t] = g_psq[idx];
    __syncthreads();
    for (int off = 128; off > 0; off >>= 1) {
        if (t < off) { rs[t] += rs[t + off]; rq[t] += rq[t + off]; }
        __syncthreads();
    }
    if (t == 0) {
        const float invN = 1.0f / (float)(NB * NS);
        float mean = rs[0] * invN;
        float var  = rq[0] * invN - mean * mean;
        g_mean[col] = mean;
        g_inv[col]  = rsqrtf(var + EPS_V);
    }
}

// ---------------------------------------------------------------------------
// Pass 3: gate + scores + masked softmax + attn @ key. One block per (b,f).
// ---------------------------------------------------------------------------
__global__ void __launch_bounds__(256) pass3_kernel(
    const float* __restrict__ key, const float* __restrict__ alpha,
    const float* __restrict__ W_o, const float* __restrict__ b_o,
    const int* __restrict__ seqnum, float* __restrict__ out)
{
    __shared__ float h_sm[NS * NH];
    __shared__ float inv_s[NH], nm_s[NH], wo_s[NH];
    __shared__ float sc[NS];
    __shared__ float red[256];
    __shared__ float opart[256];

    const int tid = threadIdx.x;
    const int bf  = blockIdx.x;
    const int f   = bf & 7;
    const int n   = seqnum[bf];

    {
        const __half2* hg = g_h + (size_t)bf * (NS * NH / 2);
        for (int i = tid; i < NS * NH / 2; i += 256)
            ((float2*)h_sm)[i] = __half22float2(hg[i]);
    }
    if (tid < NH) {
        float m  = g_mean[f * NH + tid];
        float iv = g_inv [f * NH + tid];
        inv_s[tid] = iv;
        nm_s[tid]  = -m * iv;
        wo_s[tid]  = W_o[f * NH + tid];
    }
    const float al  = alpha[f];
    const float oma = 1.0f - al;
    __syncthreads();

    float score = -3.0e38f;
    if (tid < n) {
        float s = b_o[f];
        const float* hr = h_sm + tid * NH;
        #pragma unroll 6
        for (int j = 0; j < NH; ++j) {
            float v = hr[j];
            float z = fmaf(v, inv_s[j], nm_s[j]);
            float p = fast_sigmoid(z);
            float g = fmaf(oma, p, al) * v;
            s = fmaf(g, wo_s[j], s);
        }
        score = s;
    }
    red[tid] = score;
    __syncthreads();
    for (int off = 128; off > 0; off >>= 1) {
        if (tid < off) red[tid] = fmaxf(red[tid], red[tid + off]);
        __syncthreads();
    }
    const float mx = red[0];
    __syncthreads();
    float e = 0.0f;
    if (tid < n) {
        e = __expf(score - mx);
        sc[tid] = e;
    }
    red[tid] = e;
    __syncthreads();
    for (int off = 128; off > 0; off >>= 1) {
        if (tid < off) red[tid] += red[tid + off];
        __syncthreads();
    }
    const float denom = red[0];

    const int d = tid & 63;
    const int g = tid >> 6;
    const float* kb = key + (size_t)bf * (NS * ND);
    float a0 = 0.0f;
    for (int s = g; s < n; s += 4)
        a0 = fmaf(sc[s], kb[s * ND + d], a0);
    opart[tid] = a0;
    __syncthreads();
    if (tid < ND) {
        float o = opart[tid] + opart[tid + 64] + opart[tid + 128] + opart[tid + 192];
        out[(size_t)bf * ND + tid] = o / denom;
    }
}

// ---------------------------------------------------------------------------
extern "C" void kernel_launch(void* const* d_in, const int* in_sizes, int n_in,
                              void* d_out, int out_size)
{
    const float* q      = (const float*)d_in[0];
    const float* key    = (const float*)d_in[1];
    const float* W_h    = (const float*)d_in[2];
    const float* b_h    = (const float*)d_in[3];
    const float* alpha  = (const float*)d_in[4];
    const float* W_o    = (const float*)d_in[5];
    const float* b_o    = (const float*)d_in[6];
    const int*   seqn   = (const int*)d_in[7];
    float* out = (float*)d_out;

    cudaFuncSetAttribute(pass1_kernel,
                         cudaFuncAttributeMaxDynamicSharedMemorySize,
                         PASS1_SMEM_BYTES);

    pass1_kernel<<<NBF, P1_THREADS, PASS1_SMEM_BYTES>>>(q, key, W_h, b_h);
    kstats_kernel<<<NSTAT, 256>>>();
    pass3_kernel<<<NBF, 256>>>(key, alpha, W_o, b_o, seqn, out);
}

// round 7
// speedup vs baseline: 1.2672x; 1.1151x over previous
#include <cuda_runtime.h>
#include <cuda_fp16.h>
#include <cstdint>

// Shapes
#define NB 256
#define NF 8
#define NS 200
#define ND 64
#define NH 36
#define NBF (NB*NF)          // 2048
#define NSTAT (NF*NH)        // 288
#define EPS_V 1e-3f

#define NTILES 400           // tiles of 128 rows over NB*NS=51200 rows per f
#define P1T 256
#define P1GRID (NF*NTILES)   // 3200

// ---- pass1 shared memory (floats) ----
// A_s:   [0,2560)      [k=64][half=2][20] (cols 18,19 zero)
// qh_s:  [2560,2632)   [2][36]
// sp_s:  [2632,2920)   288 partials
// key_s: [3072,11776)  [128][68] row-major; reused as h staging [128][38]
#define SM_A 0
#define SM_QH 2560
#define SM_SP 2632
#define SM_KEY 3072
#define KPAD 68
#define HPAD 38
#define P1_SMEM_FLOATS (SM_KEY + 128*KPAD)         // 11776
#define P1_SMEM_BYTES  (P1_SMEM_FLOATS*4)          // 47104

// Scratch (no allocs -> device globals)
__device__ __half2 g_h[(size_t)NBF * (NS * NH / 2)];   // fp16 hidden acts
__device__ float g_psum[P1GRID * NH];
__device__ float g_psq [P1GRID * NH];
__device__ float g_mean[NSTAT];
__device__ float g_inv [NSTAT];

union F4U2 { float4 f4; ulonglong2 u2; };
union F2U1 { float2 f2; unsigned long long u; };

__device__ __forceinline__ unsigned long long pack2(float x) {
    unsigned long long r;
    asm("mov.b64 %0, {%1, %1};" : "=l"(r) : "f"(x));
    return r;
}
__device__ __forceinline__ void fma2(unsigned long long &acc,
                                     unsigned long long a,
                                     unsigned long long b) {
    asm("fma.rn.f32x2 %0, %1, %2, %0;" : "+l"(acc) : "l"(a), "l"(b));
}

// FFMA-only sigmoid (no MUFU pressure)
__device__ __forceinline__ float fast_sigmoid(float z) {
    float x = -z * 1.4426950408889634f;
    x = fminf(fmaxf(x, -30.0f), 30.0f);
    float n = rintf(x);
    float fr = x - n;
    float p = 0.0013333558f;
    p = fmaf(p, fr, 0.009618129f);
    p = fmaf(p, fr, 0.055504109f);
    p = fmaf(p, fr, 0.24022651f);
    p = fmaf(p, fr, 0.69314718f);
    p = fmaf(p, fr, 1.0f);
    float sc = __int_as_float(((int)n + 127) << 23);
    float e = p * sc;                 // exp(-z)
    float w = 1.0f + e;
    float r = __int_as_float(0x7EF311C3 - __float_as_int(w));
    r = r * (2.0f - w * r);
    r = r * (2.0f - w * r);
    return r;
}

// ---------------------------------------------------------------------------
// Pass 1: per-CTA 128-row tile of K_f @ A_f. h = key@A + qh[b].
// A = W_k - W_d ; qh = q@(W_q+W_d)+b_h. Thread = (row, col-half).
// ---------------------------------------------------------------------------
__global__ void __launch_bounds__(P1T, 4) pass1_kernel(
    const float* __restrict__ q, const float* __restrict__ key,
    const float* __restrict__ W_h, const float* __restrict__ b_h)
{
    extern __shared__ float sm[];
    float* A_s   = sm + SM_A;
    float* qh_sm = sm + SM_QH;
    float* sp_s  = sm + SM_SP;
    float* key_s = sm + SM_KEY;   // [128][68]
    float* h_st  = sm + SM_KEY;   // reuse: [128][38]

    const int t = threadIdx.x;
    const int f    = blockIdx.x / NTILES;
    const int tile = blockIdx.x - f * NTILES;
    const int g0 = tile * 128;
    const int b0 = g0 / NS;
    const float* Wf = W_h + f * (3 * ND * NH);

    // A_s[k][half*20 + cc] = W_k - W_d (cc<18), zero pad
    #pragma unroll
    for (int it = 0; it < 10; ++it) {
        int i = t + it * P1T;            // 0..2559
        int k = i / 40, c = i - k * 40;
        int half = c / 20, cc = c - half * 20;
        float v = 0.0f;
        if (cc < 18) {
            int j = half * 18 + cc;
            v = Wf[k * NH + j] - Wf[(2 * ND + k) * NH + j];
        }
        A_s[i] = v;
    }

    // key tile -> row-major padded smem (coalesced LDG.128)
    const float4* kg = (const float4*)key;
    #pragma unroll
    for (int it = 0; it < 8; ++it) {
        int i = t + it * P1T;            // 0..2047
        int row = i >> 4, c4 = i & 15;
        int g = g0 + row;
        int b = g / NS, s = g - b * NS;
        float4 v = kg[((size_t)(b * NF + f) * NS + s) * 16 + c4];
        *(float4*)(key_s + row * KPAD + c4 * 4) = v;
    }

    // qh partials: 144 threads = (bb:2) x (j:36) x (c:2 k-chunks of 32)
    if (t < 144) {
        int bb = t / 72, rr = t - bb * 72;
        int j = rr >> 1, c = rr & 1;
        int b = b0 + bb; if (b > NB - 1) b = NB - 1;
        const float* qr = q + (size_t)(b * NF + f) * ND;
        float s = 0.0f;
        #pragma unroll 4
        for (int kk = c * 32; kk < c * 32 + 32; ++kk)
            s += qr[kk] * (Wf[(ND + kk) * NH + j] + Wf[(2 * ND + kk) * NH + j]);
        sp_s[t] = s;
    }
    __syncthreads();

    if (t < 72) {
        int bb = t / 36, j = t - bb * 36;
        qh_sm[t] = b_h[f * NH + j] + sp_s[bb * 72 + j * 2] + sp_s[bb * 72 + j * 2 + 1];
    }
    __syncthreads();

    // ---- main GEMM: all 256 threads, thread=(row, half), 9 fma2 accs ----
    const int hf = t >> 7;         // 0/1
    const int r  = t & 127;
    const int g  = g0 + r;
    const int bsel = (g >= (b0 + 1) * NS) ? 1 : 0;

    unsigned long long acc[9];
    {
        const float* qh = qh_sm + bsel * 36 + hf * 18;
        #pragma unroll
        for (int j = 0; j < 9; ++j)
            acc[j] = *(const unsigned long long*)(qh + 2 * j);
    }
    const float* krow = key_s + r * KPAD;
    const float* ab = A_s + hf * 20;
    #pragma unroll 2
    for (int k0 = 0; k0 < ND; k0 += 4) {
        float4 k4 = *(const float4*)(krow + k0);
        const float kk4[4] = {k4.x, k4.y, k4.z, k4.w};
        #pragma unroll
        for (int e = 0; e < 4; ++e) {
            unsigned long long kk = pack2(kk4[e]);
            const float* ar = ab + (k0 + e) * 40;
            F4U2 a01; a01.f4 = *(const float4*)(ar);
            F4U2 a23; a23.f4 = *(const float4*)(ar + 4);
            F4U2 a45; a45.f4 = *(const float4*)(ar + 8);
            F4U2 a67; a67.f4 = *(const float4*)(ar + 12);
            F2U1 a8;  a8.f2  = *(const float2*)(ar + 16);
            fma2(acc[0], a01.u2.x, kk);
            fma2(acc[1], a01.u2.y, kk);
            fma2(acc[2], a23.u2.x, kk);
            fma2(acc[3], a23.u2.y, kk);
            fma2(acc[4], a45.u2.x, kk);
            fma2(acc[5], a45.u2.y, kk);
            fma2(acc[6], a67.u2.x, kk);
            fma2(acc[7], a67.u2.y, kk);
            fma2(acc[8], a8.u,     kk);
        }
    }
    __syncthreads();   // all warps done reading key_s -> safe to overwrite

    {
        float* hr = h_st + r * HPAD + hf * 18;
        #pragma unroll
        for (int j = 0; j < 9; ++j) {
            F2U1 u; u.u = acc[j];
            *(float2*)(hr + 2 * j) = u.f2;
        }
    }
    __syncthreads();

    // fp16 copy-out: 2304 half2
    #pragma unroll
    for (int it = 0; it < 9; ++it) {
        int i = t + it * P1T;           // 0..2303
        int row = i / 18, e = i - row * 18;
        int gg = g0 + row;
        int b = gg / NS, s = gg - b * NS;
        float2 v = *(const float2*)(h_st + row * HPAD + 2 * e);
        g_h[((size_t)(b * NF + f) * NS + s) * 18 + e] = __float22half2_rn(v);
    }
    // per-CTA stat partials: 144 threads = (j:36) x (c:4 chunks of 32 rows)
    if (t < 144) {
        int j = t >> 2, c = t & 3;
        float ss = 0.f, qq = 0.f;
        #pragma unroll 4
        for (int rr = c * 32; rr < c * 32 + 32; ++rr) {
            float v = h_st[rr * HPAD + j];
            ss += v; qq += v * v;
        }
        sp_s[t] = ss;
        sp_s[144 + t] = qq;
    }
    __syncthreads();
    if (t < NH) {
        float ss = sp_s[t*4] + sp_s[t*4+1] + sp_s[t*4+2] + sp_s[t*4+3];
        float qq = sp_s[144+t*4] + sp_s[144+t*4+1] + sp_s[144+t*4+2] + sp_s[144+t*4+3];
        g_psum[blockIdx.x * NH + t] = ss;
        g_psq [blockIdx.x * NH + t] = qq;
    }
}

// ---------------------------------------------------------------------------
// Stats finalize: reduce 400 tile-partials per (f,j)
// ---------------------------------------------------------------------------
__global__ void __launch_bounds__(256) kstats_kernel()
{
    __shared__ float rs[256], rq[256];
    const int col = blockIdx.x;           // f*36 + j
    const int f = col / NH, j = col - f * NH;
    const int t = threadIdx.x;
    float ss = 0.f, qq = 0.f;
    for (int i = t; i < NTILES; i += 256) {
        ss += g_psum[(f * NTILES + i) * NH + j];
        qq += g_psq [(f * NTILES + i) * NH + j];
    }
    rs[t] = ss; rq[t] = qq;
    __syncthreads();
    for (int off = 128; off > 0; off >>= 1) {
        if (t < off) { rs[t] += rs[t + off]; rq[t] += rq[t + off]; }
        __syncthreads();
    }
    if (t == 0) {
        const float invN = 1.0f / (float)(NB * NS);
        float mean = rs[0] * invN;
        float var  = rq[0] * invN - mean * mean;
        g_mean[col] = mean;
        g_inv[col]  = rsqrtf(var + EPS_V);
    }
}

// ---------------------------------------------------------------------------
// Pass 3: gate + scores + masked softmax + attn @ key. One block per (b,f).
// ---------------------------------------------------------------------------
__global__ void __launch_bounds__(256) pass3_kernel(
    const float* __restrict__ key, const float* __restrict__ alpha,
    const float* __restrict__ W_o, const float* __restrict__ b_o,
    const int* __restrict__ seqnum, float* __restrict__ out)
{
    __shared__ float h_sm[NS * NH];
    __shared__ float inv_s[NH], nm_s[NH], wo_s[NH];
    __shared__ float sc[NS];
    __shared__ float red[256];
    __shared__ float opart[256];

    const int tid = threadIdx.x;
    const int bf  = blockIdx.x;
    const int f   = bf & 7;
    const int n   = seqnum[bf];

    {
        const __half2* hg = g_h + (size_t)bf * (NS * NH / 2);
        for (int i = tid; i < NS * NH / 2; i += 256)
            ((float2*)h_sm)[i] = __half22float2(hg[i]);
    }
    if (tid < NH) {
        float m  = g_mean[f * NH + tid];
        float iv = g_inv [f * NH + tid];
        inv_s[tid] = iv;
        nm_s[tid]  = -m * iv;
        wo_s[tid]  = W_o[f * NH + tid];
    }
    const float al  = alpha[f];
    const float oma = 1.0f - al;
    __syncthreads();

    float score = -3.0e38f;
    if (tid < n) {
        float s = b_o[f];
        const float* hr = h_sm + tid * NH;
        #pragma unroll 6
        for (int j = 0; j < NH; ++j) {
            float v = hr[j];
            float z = fmaf(v, inv_s[j], nm_s[j]);
            float p = fast_sigmoid(z);
            float g = fmaf(oma, p, al) * v;
            s = fmaf(g, wo_s[j], s);
        }
        score = s;
    }
    red[tid] = score;
    __syncthreads();
    for (int off = 128; off > 0; off >>= 1) {
        if (tid < off) red[tid] = fmaxf(red[tid], red[tid + off]);
        __syncthreads();
    }
    const float mx = red[0];
    __syncthreads();
    float e = 0.0f;
    if (tid < n) {
        e = __expf(score - mx);
        sc[tid] = e;
    }
    red[tid] = e;
    __syncthreads();
    for (int off = 128; off > 0; off >>= 1) {
        if (tid < off) red[tid] += red[tid + off];
        __syncthreads();
    }
    const float denom = red[0];

    const int d = tid & 63;
    const int g = tid >> 6;
    const float* kb = key + (size_t)bf * (NS * ND);
    float a0 = 0.0f;
    for (int s = g; s < n; s += 4)
        a0 = fmaf(sc[s], kb[s * ND + d], a0);
    opart[tid] = a0;
    __syncthreads();
    if (tid < ND) {
        float o = opart[tid] + opart[tid + 64] + opart[tid + 128] + opart[tid + 192];
        out[(size_t)bf * ND + tid] = o / denom;
    }
}

// ---------------------------------------------------------------------------
extern "C" void kernel_launch(void* const* d_in, const int* in_sizes, int n_in,
                              void* d_out, int out_size)
{
    const float* q      = (const float*)d_in[0];
    const float* key    = (const float*)d_in[1];
    const float* W_h    = (const float*)d_in[2];
    const float* b_h    = (const float*)d_in[3];
    const float* alpha  = (const float*)d_in[4];
    const float* W_o    = (const float*)d_in[5];
    const float* b_o    = (const float*)d_in[6];
    const int*   seqn   = (const int*)d_in[7];
    float* out = (float*)d_out;

    cudaFuncSetAttribute(pass1_kernel,
                         cudaFuncAttributeMaxDynamicSharedMemorySize,
                         P1_SMEM_BYTES);

    pass1_kernel<<<P1GRID, P1T, P1_SMEM_BYTES>>>(q, key, W_h, b_h);
    kstats_kernel<<<NSTAT, 256>>>();
    pass3_kernel<<<NBF, 256>>>(key, alpha, W_o, b_o, seqn, out);
}

// round 8
// speedup vs baseline: 1.3716x; 1.0824x over previous
#include <cuda_runtime.h>
#include <cuda_fp16.h>
#include <cstdint>

// Shapes
#define NB 256
#define NF 8
#define NS 200
#define ND 64
#define NH 36
#define NBF (NB*NF)          // 2048
#define NSTAT (NF*NH)        // 288
#define EPS_V 1e-3f

#define NTILES 400           // tiles of 128 rows over NB*NS=51200 rows per f
#define P1T 128
#define P1GRID (NF*NTILES)   // 3200

// ---- pass1 shared memory (floats) ----
// A_s:   [0,2560)      [k=64][half=2][20] (cols 18,19 zero)
// qh_s:  [2560,2632)   [2][36]
// sp_s:  [2632,2920)   partials
// key_s: [3072,11776)  [128][68] row-major; reused as h staging [128][38]
#define SM_A 0
#define SM_QH 2560
#define SM_SP 2632
#define SM_KEY 3072
#define KPAD 68
#define HPAD 38
#define P1_SMEM_FLOATS (SM_KEY + 128*KPAD)         // 11776
#define P1_SMEM_BYTES  (P1_SMEM_FLOATS*4)          // 47104

// Scratch (no allocs -> device globals)
__device__ __half2 g_h[(size_t)NBF * (NS * NH / 2)];   // fp16 hidden acts
__device__ float g_psum[P1GRID * NH];
__device__ float g_psq [P1GRID * NH];
__device__ float g_mean[NSTAT];
__device__ float g_inv [NSTAT];

union F4U2 { float4 f4; ulonglong2 u2; };
union F2U1 { float2 f2; unsigned long long u; };

__device__ __forceinline__ unsigned long long pack2(float x) {
    unsigned long long r;
    asm("mov.b64 %0, {%1, %1};" : "=l"(r) : "f"(x));
    return r;
}
__device__ __forceinline__ void fma2(unsigned long long &acc,
                                     unsigned long long a,
                                     unsigned long long b) {
    asm("fma.rn.f32x2 %0, %1, %2, %0;" : "+l"(acc) : "l"(a), "l"(b));
}

// FFMA-only sigmoid (no MUFU pressure)
__device__ __forceinline__ float fast_sigmoid(float z) {
    float x = -z * 1.4426950408889634f;
    x = fminf(fmaxf(x, -30.0f), 30.0f);
    float n = rintf(x);
    float fr = x - n;
    float p = 0.0013333558f;
    p = fmaf(p, fr, 0.009618129f);
    p = fmaf(p, fr, 0.055504109f);
    p = fmaf(p, fr, 0.24022651f);
    p = fmaf(p, fr, 0.69314718f);
    p = fmaf(p, fr, 1.0f);
    float sc = __int_as_float(((int)n + 127) << 23);
    float e = p * sc;                 // exp(-z)
    float w = 1.0f + e;
    float r = __int_as_float(0x7EF311C3 - __float_as_int(w));
    r = r * (2.0f - w * r);
    r = r * (2.0f - w * r);
    return r;
}

// ---------------------------------------------------------------------------
// Pass 1: per-CTA 128-row tile of K_f @ A_f. h = key@A + qh[b].
// Thread = (row-pair, col-half): 5 A-broadcast LDS feed 18 FFMA2 (2 rows).
// ---------------------------------------------------------------------------
__global__ void __launch_bounds__(P1T, 4) pass1_kernel(
    const float* __restrict__ q, const float* __restrict__ key,
    const float* __restrict__ W_h, const float* __restrict__ b_h)
{
    extern __shared__ float sm[];
    float* A_s   = sm + SM_A;
    float* qh_sm = sm + SM_QH;
    float* sp_s  = sm + SM_SP;
    float* key_s = sm + SM_KEY;   // [128][68]
    float* h_st  = sm + SM_KEY;   // reuse: [128][38]

    const int t = threadIdx.x;
    const int f    = blockIdx.x / NTILES;
    const int tile = blockIdx.x - f * NTILES;
    const int g0 = tile * 128;
    const int b0 = g0 / NS;
    const float* Wf = W_h + f * (3 * ND * NH);

    // A_s[k][half*20 + cc] = W_k - W_d (cc<18), zero pad
    #pragma unroll
    for (int it = 0; it < 20; ++it) {
        int i = t + it * P1T;            // 0..2559
        int k = i / 40, c = i - k * 40;
        int half = c / 20, cc = c - half * 20;
        float v = 0.0f;
        if (cc < 18) {
            int j = half * 18 + cc;
            v = Wf[k * NH + j] - Wf[(2 * ND + k) * NH + j];
        }
        A_s[i] = v;
    }

    // key tile -> row-major padded smem (coalesced LDG.128)
    const float4* kg = (const float4*)key;
    #pragma unroll
    for (int it = 0; it < 16; ++it) {
        int i = t + it * P1T;            // 0..2047
        int row = i >> 4, c4 = i & 15;
        int g = g0 + row;
        int b = g / NS, s = g - b * NS;
        float4 v = kg[((size_t)(b * NF + f) * NS + s) * 16 + c4];
        *(float4*)(key_s + row * KPAD + c4 * 4) = v;
    }

    // qh: 72 threads = (bb:2) x (j:36), full 64-k dot each
    if (t < 72) {
        int bb = t / 36, j = t - bb * 36;
        int b = b0 + bb; if (b > NB - 1) b = NB - 1;
        const float* qr = q + (size_t)(b * NF + f) * ND;
        float s = b_h[f * NH + j];
        #pragma unroll 4
        for (int k = 0; k < ND; ++k)
            s += qr[k] * (Wf[(ND + k) * NH + j] + Wf[(2 * ND + k) * NH + j]);
        qh_sm[bb * 36 + j] = s;
    }
    __syncthreads();

    // ---- main GEMM: thread=(row-pair, half), 2x9 fma2 accs ----
    const int hf = t >> 6;           // 0/1
    const int rp = t & 63;           // rows 2rp, 2rp+1
    const int r0 = 2 * rp, r1 = 2 * rp + 1;
    const int bs0 = ((g0 + r0) >= (b0 + 1) * NS) ? 1 : 0;
    const int bs1 = ((g0 + r1) >= (b0 + 1) * NS) ? 1 : 0;

    unsigned long long accA[9], accB[9];
    {
        const float* qh0 = qh_sm + bs0 * 36 + hf * 18;
        const float* qh1 = qh_sm + bs1 * 36 + hf * 18;
        #pragma unroll
        for (int j = 0; j < 9; ++j) {
            accA[j] = *(const unsigned long long*)(qh0 + 2 * j);
            accB[j] = *(const unsigned long long*)(qh1 + 2 * j);
        }
    }
    const float* k0p = key_s + r0 * KPAD;
    const float* k1p = key_s + r1 * KPAD;
    const float* ab = A_s + hf * 20;
    #pragma unroll 2
    for (int k0 = 0; k0 < ND; k0 += 4) {
        float4 ka = *(const float4*)(k0p + k0);
        float4 kb = *(const float4*)(k1p + k0);
        const float kav[4] = {ka.x, ka.y, ka.z, ka.w};
        const float kbv[4] = {kb.x, kb.y, kb.z, kb.w};
        #pragma unroll
        for (int e = 0; e < 4; ++e) {
            unsigned long long kx = pack2(kav[e]);
            unsigned long long ky = pack2(kbv[e]);
            const float* ar = ab + (k0 + e) * 40;
            F4U2 a01; a01.f4 = *(const float4*)(ar);
            F4U2 a23; a23.f4 = *(const float4*)(ar + 4);
            F4U2 a45; a45.f4 = *(const float4*)(ar + 8);
            F4U2 a67; a67.f4 = *(const float4*)(ar + 12);
            F2U1 a8;  a8.f2  = *(const float2*)(ar + 16);
            fma2(accA[0], a01.u2.x, kx);  fma2(accB[0], a01.u2.x, ky);
            fma2(accA[1], a01.u2.y, kx);  fma2(accB[1], a01.u2.y, ky);
            fma2(accA[2], a23.u2.x, kx);  fma2(accB[2], a23.u2.x, ky);
            fma2(accA[3], a23.u2.y, kx);  fma2(accB[3], a23.u2.y, ky);
            fma2(accA[4], a45.u2.x, kx);  fma2(accB[4], a45.u2.x, ky);
            fma2(accA[5], a45.u2.y, kx);  fma2(accB[5], a45.u2.y, ky);
            fma2(accA[6], a67.u2.x, kx);  fma2(accB[6], a67.u2.x, ky);
            fma2(accA[7], a67.u2.y, kx);  fma2(accB[7], a67.u2.y, ky);
            fma2(accA[8], a8.u,     kx);  fma2(accB[8], a8.u,     ky);
        }
    }
    __syncthreads();   // all warps done reading key_s -> safe to overwrite

    {
        float* h0 = h_st + r0 * HPAD + hf * 18;
        float* h1 = h_st + r1 * HPAD + hf * 18;
        #pragma unroll
        for (int j = 0; j < 9; ++j) {
            F2U1 u0; u0.u = accA[j];
            F2U1 u1; u1.u = accB[j];
            *(float2*)(h0 + 2 * j) = u0.f2;
            *(float2*)(h1 + 2 * j) = u1.f2;
        }
    }
    __syncthreads();

    // fp16 copy-out: 2304 half2 over 128 threads
    #pragma unroll
    for (int it = 0; it < 18; ++it) {
        int i = t + it * P1T;           // 0..2303
        int row = i / 18, e = i - row * 18;
        int gg = g0 + row;
        int b = gg / NS, s = gg - b * NS;
        float2 v = *(const float2*)(h_st + row * HPAD + 2 * e);
        g_h[((size_t)(b * NF + f) * NS + s) * 18 + e] = __float22half2_rn(v);
    }
    // per-CTA stat partials: 72 threads = (j:36) x (c:2 chunks of 64 rows)
    if (t < 72) {
        int j = t >> 1, c = t & 1;
        float ss = 0.f, qq = 0.f;
        #pragma unroll 4
        for (int rr = c * 64; rr < c * 64 + 64; ++rr) {
            float v = h_st[rr * HPAD + j];
            ss += v; qq += v * v;
        }
        sp_s[t] = ss;
        sp_s[72 + t] = qq;
    }
    __syncthreads();
    if (t < NH) {
        float ss = sp_s[t*2] + sp_s[t*2+1];
        float qq = sp_s[72 + t*2] + sp_s[72 + t*2+1];
        g_psum[blockIdx.x * NH + t] = ss;
        g_psq [blockIdx.x * NH + t] = qq;
    }
}

// ---------------------------------------------------------------------------
// Stats finalize: reduce 400 tile-partials per (f,j)
// ---------------------------------------------------------------------------
__global__ void __launch_bounds__(256) kstats_kernel()
{
    __shared__ float rs[256], rq[256];
    const int col = blockIdx.x;           // f*36 + j
    const int f = col / NH, j = col - f * NH;
    const int t = threadIdx.x;
    float ss = 0.f, qq = 0.f;
    for (int i = t; i < NTILES; i += 256) {
        ss += g_psum[(f * NTILES + i) * NH + j];
        qq += g_psq [(f * NTILES + i) * NH + j];
    }
    rs[t] = ss; rq[t] = qq;
    __syncthreads();
    for (int off = 128; off > 0; off >>= 1) {
        if (t < off) { rs[t] += rs[t + off]; rq[t] += rq[t + off]; }
        __syncthreads();
    }
    if (t == 0) {
        const float invN = 1.0f / (float)(NB * NS);
        float mean = rs[0] * invN;
        float var  = rq[0] * invN - mean * mean;
        g_mean[col] = mean;
        g_inv[col]  = rsqrtf(var + EPS_V);
    }
}

// ---------------------------------------------------------------------------
// Pass 3: gate + scores + masked softmax + attn @ key. One block per (b,f).
// ---------------------------------------------------------------------------
__global__ void __launch_bounds__(256) pass3_kernel(
    const float* __restrict__ key, const float* __restrict__ alpha,
    const float* __restrict__ W_o, const float* __restrict__ b_o,
    const int* __restrict__ seqnum, float* __restrict__ out)
{
    __shared__ float h_sm[NS * NH];
    __shared__ float inv_s[NH], nm_s[NH], wo_s[NH];
    __shared__ float sc[NS];
    __shared__ float red[256];
    __shared__ float opart[256];

    const int tid = threadIdx.x;
    const int bf  = blockIdx.x;
    const int f   = bf & 7;
    const int n   = seqnum[bf];

    {
        const __half2* hg = g_h + (size_t)bf * (NS * NH / 2);
        for (int i = tid; i < NS * NH / 2; i += 256)
            ((float2*)h_sm)[i] = __half22float2(hg[i]);
    }
    if (tid < NH) {
        float m  = g_mean[f * NH + tid];
        float iv = g_inv [f * NH + tid];
        inv_s[tid] = iv;
        nm_s[tid]  = -m * iv;
        wo_s[tid]  = W_o[f * NH + tid];
    }
    const float al  = alpha[f];
    const float oma = 1.0f - al;
    __syncthreads();

    float score = -3.0e38f;
    if (tid < n) {
        float s = b_o[f];
        const float* hr = h_sm + tid * NH;
        #pragma unroll 6
        for (int j = 0; j < NH; ++j) {
            float v = hr[j];
            float z = fmaf(v, inv_s[j], nm_s[j]);
            float p = fast_sigmoid(z);
            float g = fmaf(oma, p, al) * v;
            s = fmaf(g, wo_s[j], s);
        }
        score = s;
    }
    red[tid] = score;
    __syncthreads();
    for (int off = 128; off > 0; off >>= 1) {
        if (tid < off) red[tid] = fmaxf(red[tid], red[tid + off]);
        __syncthreads();
    }
    const float mx = red[0];
    __syncthreads();
    float e = 0.0f;
    if (tid < n) {
        e = __expf(score - mx);
        sc[tid] = e;
    }
    red[tid] = e;
    __syncthreads();
    for (int off = 128; off > 0; off >>= 1) {
        if (tid < off) red[tid] += red[tid + off];
        __syncthreads();
    }
    const float denom = red[0];

    const int d = tid & 63;
    const int g = tid >> 6;
    const float* kb = key + (size_t)bf * (NS * ND);
    float a0 = 0.0f;
    for (int s = g; s < n; s += 4)
        a0 = fmaf(sc[s], kb[s * ND + d], a0);
    opart[tid] = a0;
    __syncthreads();
    if (tid < ND) {
        float o = opart[tid] + opart[tid + 64] + opart[tid + 128] + opart[tid + 192];
        out[(size_t)bf * ND + tid] = o / denom;
    }
}

// ---------------------------------------------------------------------------
extern "C" void kernel_launch(void* const* d_in, const int* in_sizes, int n_in,
                              void* d_out, int out_size)
{
    const float* q      = (const float*)d_in[0];
    const float* key    = (const float*)d_in[1];
    const float* W_h    = (const float*)d_in[2];
    const float* b_h    = (const float*)d_in[3];
    const float* alpha  = (const float*)d_in[4];
    const float* W_o    = (const float*)d_in[5];
    const float* b_o    = (const float*)d_in[6];
    const int*   seqn   = (const int*)d_in[7];
    float* out = (float*)d_out;

    cudaFuncSetAttribute(pass1_kernel,
                         cudaFuncAttributeMaxDynamicSharedMemorySize,
                         P1_SMEM_BYTES);

    pass1_kernel<<<P1GRID, P1T, P1_SMEM_BYTES>>>(q, key, W_h, b_h);
    kstats_kernel<<<NSTAT, 256>>>();
    pass3_kernel<<<NBF, 256>>>(key, alpha, W_o, b_o, seqn, out);
}